// round 1
// baseline (speedup 1.0000x reference)
#include <cuda_runtime.h>
#include <cstdint>

#define BB 2
#define NN 8192
#define CC 80
#define NW 128  /* 64-bit words per mask row = NN/64 */

/* output layout (concatenated flat float32, tuple order) */
#define OFF_BOXES 0
#define OFF_MS    (BB*NN*4)
#define OFF_LB    (OFF_MS + BB*NN)
#define OFF_KEEP  (OFF_LB + BB*NN)
#define OFF_ALL   (OFF_KEEP + BB*NN)

/* static device scratch (no allocation allowed) */
__device__ unsigned long long g_mask[BB][NN][NW];   /* 16 MB suppression bitmask (upper triangle valid) */
__device__ unsigned long long g_keys[BB][NN];       /* packed sort keys */
__device__ unsigned int       g_sorted[BB][NN];     /* sorted original indices */
__device__ int                g_valid[BB][NN];      /* validity flags */

/* ------------------------------------------------------------------ */
/* Kernel 1: sigmoid / max / argmax / box decode / valid / sort keys   */
/* one warp per anchor                                                  */
__global__ void prep_kernel(const float* __restrict__ logits,
                            const float* __restrict__ deltas,
                            const float* __restrict__ anchors,
                            float* __restrict__ out)
{
    int wid  = (blockIdx.x * blockDim.x + threadIdx.x) >> 5;
    int lane = threadIdx.x & 31;
    if (wid >= BB * NN) return;
    int b = wid / NN, n = wid % NN;

    const float* lg = logits + (size_t)wid * CC;
    float* as_out   = out + OFF_ALL + (size_t)wid * CC;

    float v0 = lg[lane];
    float v1 = lg[lane + 32];
    float v2 = (lane < 16) ? lg[lane + 64] : -INFINITY;

    as_out[lane]      = 1.0f / (1.0f + expf(-v0));
    as_out[lane + 32] = 1.0f / (1.0f + expf(-v1));
    if (lane < 16) as_out[lane + 64] = 1.0f / (1.0f + expf(-v2));

    /* local argmax, ascending index order -> first-max wins */
    float mv = v0; int mi = lane;
    if (v1 > mv) { mv = v1; mi = lane + 32; }
    if (v2 > mv) { mv = v2; mi = lane + 64; }

    /* warp reduce: max value, tie -> lower index */
    for (int off = 16; off; off >>= 1) {
        float ov = __shfl_down_sync(0xffffffffu, mv, off);
        int   oi = __shfl_down_sync(0xffffffffu, mi, off);
        if (ov > mv || (ov == mv && oi < mi)) { mv = ov; mi = oi; }
    }

    if (lane == 0) {
        float ms = 1.0f / (1.0f + expf(-mv));
        out[OFF_MS + wid] = ms;
        out[OFF_LB + wid] = (float)mi;

        const float* dl = deltas  + (size_t)wid * 4;
        const float* an = anchors + (size_t)n * 4;
        float a0 = an[0], a1 = an[1], a2 = an[2], a3 = an[3];
        float aw = a2 - a0, ah = a3 - a1;
        float acx = a0 + 0.5f * aw, acy = a1 + 0.5f * ah;
        float dx = dl[0], dy = dl[1];
        float dw = fminf(dl[2], 4.0f), dh = fminf(dl[3], 4.0f);
        float pcx = dx * aw + acx, pcy = dy * ah + acy;
        float pw = expf(dw) * aw, ph = expf(dh) * ah;
        float x1 = fminf(fmaxf(pcx - 0.5f * pw, 0.0f), 1.0f);
        float y1 = fminf(fmaxf(pcy - 0.5f * ph, 0.0f), 1.0f);
        float x2 = fminf(fmaxf(pcx + 0.5f * pw, 0.0f), 1.0f);
        float y2 = fminf(fmaxf(pcy + 0.5f * ph, 0.0f), 1.0f);

        float* bo = out + OFF_BOXES + (size_t)wid * 4;
        bo[0] = x1; bo[1] = y1; bo[2] = x2; bo[3] = y2;

        float w = x2 - x1, h = y2 - y1;
        int valid = (ms > 0.5f) && (w > 0.01f) && (h > 0.01f) &&
                    (w < 0.99f) && (h < 0.99f);
        g_valid[b][n] = valid;

        unsigned int ksb = ~__float_as_uint(ms);   /* ms > 0 -> bits monotonic */
        g_keys[b][n] = ((unsigned long long)ksb << 32) | (unsigned int)n;
    }
}

/* ------------------------------------------------------------------ */
/* Kernel 2: bitonic sort of 8192 packed keys per batch (ascending     */
/* packed == descending score, stable by original index)               */
extern __shared__ unsigned long long s_keys[];
__global__ void sort_kernel()
{
    int b = blockIdx.x;
    for (int i = threadIdx.x; i < NN; i += blockDim.x)
        s_keys[i] = g_keys[b][i];
    __syncthreads();

    for (int k = 2; k <= NN; k <<= 1) {
        for (int j = k >> 1; j > 0; j >>= 1) {
            for (int i = threadIdx.x; i < NN; i += blockDim.x) {
                int ixj = i ^ j;
                if (ixj > i) {
                    unsigned long long a = s_keys[i];
                    unsigned long long c = s_keys[ixj];
                    bool up = ((i & k) == 0);
                    if (up ? (a > c) : (a < c)) { s_keys[i] = c; s_keys[ixj] = a; }
                }
            }
            __syncthreads();
        }
    }
    for (int i = threadIdx.x; i < NN; i += blockDim.x)
        g_sorted[b][i] = (unsigned int)(s_keys[i] & 0xffffffffull);
}

/* ------------------------------------------------------------------ */
/* Kernel 3: suppression bitmask, 64x64 tiles, col_block >= row_block  */
__global__ void mask_kernel(const float* __restrict__ out)
{
    int cb = blockIdx.x, rb = blockIdx.y, b = blockIdx.z;
    if (cb < rb) return;
    int t = threadIdx.x;  /* 64 threads */

    __shared__ float sx1[64], sy1[64], sx2[64], sy2[64], sar[64];

    int cj = cb * 64 + t;
    unsigned int jidx = g_sorted[b][cj];
    float4 cbx = *(const float4*)(out + OFF_BOXES + ((size_t)b * NN + jidx) * 4);
    sx1[t] = cbx.x; sy1[t] = cbx.y; sx2[t] = cbx.z; sy2[t] = cbx.w;
    sar[t] = (cbx.z - cbx.x) * (cbx.w - cbx.y);
    __syncthreads();

    int i = rb * 64 + t;
    unsigned int iidx = g_sorted[b][i];
    float4 rbx = *(const float4*)(out + OFF_BOXES + ((size_t)b * NN + iidx) * 4);
    float ar = (rbx.z - rbx.x) * (rbx.w - rbx.y);

    unsigned long long m = 0;
#pragma unroll 8
    for (int j = 0; j < 64; j++) {
        float ix1 = fmaxf(rbx.x, sx1[j]);
        float iy1 = fmaxf(rbx.y, sy1[j]);
        float ix2 = fminf(rbx.z, sx2[j]);
        float iy2 = fminf(rbx.w, sy2[j]);
        float iw = fmaxf(ix2 - ix1, 0.0f);
        float ih = fmaxf(iy2 - iy1, 0.0f);
        float inter = iw * ih;
        float uni = ar + sar[j] - inter;
        if (inter > 0.5f * fmaxf(uni, 1e-9f)) m |= 1ull << j;
    }
    if (cb == rb) m &= ~(1ull << t);   /* clear self bit */
    g_mask[b][i][cb] = m;
}

/* ------------------------------------------------------------------ */
/* Kernel 4: greedy gather (exact greedy-NMS semantics), 1 block/batch */
__global__ void gather_kernel(float* __restrict__ out)
{
    int b = blockIdx.x;
    int t = threadIdx.x;   /* 128 threads */

    __shared__ unsigned long long removed[NW], validw[NW], diag[64], keepw[NW];
    __shared__ int krows[64];
    __shared__ int kcnt;
    __shared__ int sidx[NN];   /* 32 KB */

    for (int i = t; i < NN; i += 128) sidx[i] = (int)g_sorted[b][i];
    removed[t] = 0ull;
    __syncthreads();

    {   /* validity bitmask in sorted order */
        unsigned long long w = 0ull;
        int base = t * 64;
        for (int k2 = 0; k2 < 64; k2++)
            if (g_valid[b][sidx[base + k2]]) w |= 1ull << k2;
        validw[t] = w;
    }
    __syncthreads();

    for (int c = 0; c < NW; c++) {
        if (t < 64) diag[t] = g_mask[b][c * 64 + t][c];
        __syncthreads();

        if (t == 0) {
            unsigned long long pending = validw[c] & ~removed[c];
            unsigned long long remloc  = removed[c];
            unsigned long long kept = 0ull;
            int cnt = 0;
            while (pending) {
                int i = __ffsll((long long)pending) - 1;
                pending &= pending - 1;
                if (!((remloc >> i) & 1ull)) {
                    kept |= 1ull << i;
                    remloc |= diag[i];
                    krows[cnt++] = c * 64 + i;
                }
            }
            keepw[c] = kept;
            kcnt = cnt;
        }
        __syncthreads();

        int cnt = kcnt;
        if (t > c && cnt) {
            unsigned long long r = removed[t];
            int q = 0;
            for (; q + 4 <= cnt; q += 4) {   /* independent loads -> MLP */
                unsigned long long m0 = g_mask[b][krows[q]][t];
                unsigned long long m1 = g_mask[b][krows[q + 1]][t];
                unsigned long long m2 = g_mask[b][krows[q + 2]][t];
                unsigned long long m3 = g_mask[b][krows[q + 3]][t];
                r |= m0 | m1 | m2 | m3;
            }
            for (; q < cnt; q++) r |= g_mask[b][krows[q]][t];
            removed[t] = r;
        }
        __syncthreads();
    }

    /* scatter keep back to original order */
    for (int i = t; i < NN; i += 128) {
        int w = i >> 6, bit = i & 63;
        float kv = (float)((keepw[w] >> bit) & 1ull);
        out[OFF_KEEP + b * NN + sidx[i]] = kv;
    }
}

/* ------------------------------------------------------------------ */
extern "C" void kernel_launch(void* const* d_in, const int* in_sizes, int n_in,
                              void* d_out, int out_size)
{
    (void)in_sizes; (void)n_in; (void)out_size;
    const float* logits  = (const float*)d_in[0];
    const float* deltas  = (const float*)d_in[1];
    const float* anchors = (const float*)d_in[2];
    float* out = (float*)d_out;

    /* opt in to 64 KB dynamic smem for the sorter (idempotent, capture-safe) */
    cudaFuncSetAttribute(sort_kernel,
                         cudaFuncAttributeMaxDynamicSharedMemorySize,
                         NN * (int)sizeof(unsigned long long));

    prep_kernel<<<(BB * NN * 32 + 255) / 256, 256>>>(logits, deltas, anchors, out);
    sort_kernel<<<BB, 1024, NN * sizeof(unsigned long long)>>>();
    {
        dim3 grid(NW, NW, BB);
        mask_kernel<<<grid, 64>>>(out);
    }
    gather_kernel<<<BB, 128>>>(out);
}

// round 2
// speedup vs baseline: 2.4295x; 2.4295x over previous
#include <cuda_runtime.h>
#include <cstdint>

#define BB 2
#define NN 8192
#define CC 80
#define NW 128  /* 64-bit words per mask row = NN/64 */

typedef unsigned long long u64;
typedef unsigned int u32;

/* output layout (concatenated flat float32, tuple order) */
#define OFF_BOXES 0
#define OFF_MS    (BB*NN*4)
#define OFF_LB    (OFF_MS + BB*NN)
#define OFF_KEEP  (OFF_LB + BB*NN)
#define OFF_ALL   (OFF_KEEP + BB*NN)

/* static device scratch (no allocation allowed) */
__device__ u64 g_mask[BB][NN][NW];    /* 16 MB suppression bitmask (upper triangle valid) */
__device__ u64 g_diagT[BB][NW][64];   /* transposed 64x64 diagonal tiles */
__device__ u64 g_keys[BB][NN];        /* packed sort keys */
__device__ u32 g_sorted[BB][NN];      /* sorted original indices */
__device__ int g_valid[BB][NN];       /* validity flags */

/* ------------------------------------------------------------------ */
/* Kernel 1: sigmoid / max / argmax / box decode / valid / sort keys   */
__global__ void prep_kernel(const float* __restrict__ logits,
                            const float* __restrict__ deltas,
                            const float* __restrict__ anchors,
                            float* __restrict__ out)
{
    int wid  = (blockIdx.x * blockDim.x + threadIdx.x) >> 5;
    int lane = threadIdx.x & 31;
    if (wid >= BB * NN) return;
    int b = wid / NN, n = wid % NN;

    const float* lg = logits + (size_t)wid * CC;
    float* as_out   = out + OFF_ALL + (size_t)wid * CC;

    float v0 = lg[lane];
    float v1 = lg[lane + 32];
    float v2 = (lane < 16) ? lg[lane + 64] : -INFINITY;

    as_out[lane]      = 1.0f / (1.0f + expf(-v0));
    as_out[lane + 32] = 1.0f / (1.0f + expf(-v1));
    if (lane < 16) as_out[lane + 64] = 1.0f / (1.0f + expf(-v2));

    float mv = v0; int mi = lane;
    if (v1 > mv) { mv = v1; mi = lane + 32; }
    if (v2 > mv) { mv = v2; mi = lane + 64; }

    for (int off = 16; off; off >>= 1) {
        float ov = __shfl_down_sync(0xffffffffu, mv, off);
        int   oi = __shfl_down_sync(0xffffffffu, mi, off);
        if (ov > mv || (ov == mv && oi < mi)) { mv = ov; mi = oi; }
    }

    if (lane == 0) {
        float ms = 1.0f / (1.0f + expf(-mv));
        out[OFF_MS + wid] = ms;
        out[OFF_LB + wid] = (float)mi;

        const float* dl = deltas  + (size_t)wid * 4;
        const float* an = anchors + (size_t)n * 4;
        float a0 = an[0], a1 = an[1], a2 = an[2], a3 = an[3];
        float aw = a2 - a0, ah = a3 - a1;
        float acx = a0 + 0.5f * aw, acy = a1 + 0.5f * ah;
        float dx = dl[0], dy = dl[1];
        float dw = fminf(dl[2], 4.0f), dh = fminf(dl[3], 4.0f);
        float pcx = dx * aw + acx, pcy = dy * ah + acy;
        float pw = expf(dw) * aw, ph = expf(dh) * ah;
        float x1 = fminf(fmaxf(pcx - 0.5f * pw, 0.0f), 1.0f);
        float y1 = fminf(fmaxf(pcy - 0.5f * ph, 0.0f), 1.0f);
        float x2 = fminf(fmaxf(pcx + 0.5f * pw, 0.0f), 1.0f);
        float y2 = fminf(fmaxf(pcy + 0.5f * ph, 0.0f), 1.0f);

        float* bo = out + OFF_BOXES + (size_t)wid * 4;
        bo[0] = x1; bo[1] = y1; bo[2] = x2; bo[3] = y2;

        float w = x2 - x1, h = y2 - y1;
        int valid = (ms > 0.5f) && (w > 0.01f) && (h > 0.01f) &&
                    (w < 0.99f) && (h < 0.99f);
        g_valid[b][n] = valid;

        u32 ksb = ~__float_as_uint(ms);
        g_keys[b][n] = ((u64)ksb << 32) | (u32)n;
    }
}

/* ------------------------------------------------------------------ */
/* Kernel 2: bitonic sort of 8192 packed keys per batch                */
extern __shared__ u64 s_keys[];
__global__ void sort_kernel()
{
    int b = blockIdx.x;
    for (int i = threadIdx.x; i < NN; i += blockDim.x)
        s_keys[i] = g_keys[b][i];
    __syncthreads();

    for (int k = 2; k <= NN; k <<= 1) {
        for (int j = k >> 1; j > 0; j >>= 1) {
            for (int i = threadIdx.x; i < NN; i += blockDim.x) {
                int ixj = i ^ j;
                if (ixj > i) {
                    u64 a = s_keys[i];
                    u64 c = s_keys[ixj];
                    bool up = ((i & k) == 0);
                    if (up ? (a > c) : (a < c)) { s_keys[i] = c; s_keys[ixj] = a; }
                }
            }
            __syncthreads();
        }
    }
    for (int i = threadIdx.x; i < NN; i += blockDim.x)
        g_sorted[b][i] = (u32)(s_keys[i] & 0xffffffffull);
}

/* ------------------------------------------------------------------ */
/* Kernel 3: suppression bitmask; linearized upper-triangle tiles.     */
/* For diagonal tiles also emit the transposed tile into g_diagT.      */
__global__ void mask_kernel(const float* __restrict__ out)
{
    int b = blockIdx.y;
    int L = blockIdx.x;                 /* 0 .. NW*(NW+1)/2 - 1 */
    /* decode: cb such that cb*(cb+1)/2 <= L < (cb+1)*(cb+2)/2 ; rb = L - cb*(cb+1)/2 */
    int cb = (int)((sqrtf(8.0f * (float)L + 1.0f) - 1.0f) * 0.5f);
    while ((cb + 1) * (cb + 2) / 2 <= L) cb++;
    while (cb * (cb + 1) / 2 > L) cb--;
    int rb = L - cb * (cb + 1) / 2;     /* rb <= cb */

    int t = threadIdx.x;  /* 64 threads */

    __shared__ float sx1[64], sy1[64], sx2[64], sy2[64], sar[64];
    __shared__ u64 srow[64];

    int cj = cb * 64 + t;
    u32 jidx = g_sorted[b][cj];
    float4 cbx = *(const float4*)(out + OFF_BOXES + ((size_t)b * NN + jidx) * 4);
    sx1[t] = cbx.x; sy1[t] = cbx.y; sx2[t] = cbx.z; sy2[t] = cbx.w;
    sar[t] = (cbx.z - cbx.x) * (cbx.w - cbx.y);
    __syncthreads();

    int i = rb * 64 + t;
    u32 iidx = g_sorted[b][i];
    float4 rbx = *(const float4*)(out + OFF_BOXES + ((size_t)b * NN + iidx) * 4);
    float ar = (rbx.z - rbx.x) * (rbx.w - rbx.y);

    u64 m = 0;
#pragma unroll 8
    for (int j = 0; j < 64; j++) {
        float ix1 = fmaxf(rbx.x, sx1[j]);
        float iy1 = fmaxf(rbx.y, sy1[j]);
        float ix2 = fminf(rbx.z, sx2[j]);
        float iy2 = fminf(rbx.w, sy2[j]);
        float iw = fmaxf(ix2 - ix1, 0.0f);
        float ih = fmaxf(iy2 - iy1, 0.0f);
        float inter = iw * ih;
        float uni = ar + sar[j] - inter;
        if (inter > 0.5f * fmaxf(uni, 1e-9f)) m |= 1ull << j;
    }
    if (cb == rb) m &= ~(1ull << t);   /* clear self bit */
    g_mask[b][i][cb] = m;

    if (cb == rb) {
        /* build transposed tile: colT[t] bit j = row j suppresses box t */
        srow[t] = m;
        __syncthreads();
        u64 ct = 0;
#pragma unroll 8
        for (int j = 0; j < 64; j++)
            ct |= ((srow[j] >> t) & 1ull) << j;
        g_diagT[b][rb][t] = ct;
    }
}

/* ------------------------------------------------------------------ */
/* Kernel 4: greedy gather. 1 block/batch, 1024 threads.               */
/* Per 64-chunk: warp-0 fixed-point keep resolution (ballot only),     */
/* then 8-way-parallel OR of kept rows into later removed words.       */
__global__ __launch_bounds__(1024, 1)
void gather_kernel(float* __restrict__ out)
{
    extern __shared__ u64 sm[];
    u64* colTall = sm;                 /* NW*64 = 8192 words (64 KB) */
    u64* removed = colTall + NW * 64;  /* NW */
    u64* keepw   = removed + NW;       /* NW */
    u32* vw32    = (u32*)(keepw + NW); /* 2*NW u32 (1 KB) */
    int* krows   = (int*)(vw32 + 2 * NW); /* 64 */
    __shared__ int kcnt;

    int b = blockIdx.x;
    int t = threadIdx.x;   /* 1024 */
    int lane = t & 31;

    /* preload all transposed diag tiles (coalesced) */
    for (int i = t; i < NW * 64; i += 1024)
        colTall[i] = g_diagT[b][0][i];

    if (t < NW) { removed[t] = 0ull; keepw[t] = 0ull; }

    /* validity bits in sorted order via ballot */
    for (int p = 0; p < NN; p += 1024) {
        int i = p + t;
        u32 si = g_sorted[b][i];
        int v = g_valid[b][si];
        u32 bal = __ballot_sync(0xffffffffu, v != 0);
        if (lane == 0) vw32[i >> 5] = bal;
    }
    __syncthreads();

    int w   = t & 127;
    int sub = t >> 7;

    for (int c = 0; c < NW; c++) {
        if (t < 32) {
            u64 veff = (((u64)vw32[2 * c + 1] << 32) | (u64)vw32[2 * c])
                       & ~removed[c];
            u64 ct_lo = colTall[c * 64 + lane];
            u64 ct_hi = colTall[c * 64 + 32 + lane];
            u64 blo = (1ull << lane) - 1;               /* bits below lane    */
            u64 bhi = (1ull << (lane + 32)) - 1;        /* bits below lane+32 */
            bool v0 = (veff >> lane) & 1;
            bool v1 = (veff >> (lane + 32)) & 1;

            u64 k = veff;
            for (int it = 0; it < 70; it++) {
                bool c0 = v0 && ((ct_lo & k & blo) == 0);
                bool c1 = v1 && ((ct_hi & k & bhi) == 0);
                u32 lo = __ballot_sync(0xffffffffu, c0);
                u32 hi = __ballot_sync(0xffffffffu, c1);
                u64 kn = (u64)lo | ((u64)hi << 32);
                if (kn == k) break;
                k = kn;
            }

            if ((k >> lane) & 1)
                krows[__popcll(k & blo)] = c * 64 + lane;
            if ((k >> (lane + 32)) & 1)
                krows[__popcll(k & bhi)] = c * 64 + lane + 32;
            if (lane == 0) { keepw[c] = k; kcnt = __popcll(k); }
        }
        __syncthreads();

        int cnt = kcnt;
        if (w > c && sub < cnt) {
            u64 r = 0;
            for (int q = sub; q < cnt; q += 8)
                r |= g_mask[b][krows[q]][w];
            if (r) atomicOr(&removed[w], r);
        }
        __syncthreads();
    }

    /* scatter keep back to original order */
    for (int i = t; i < NN; i += 1024) {
        u32 si = g_sorted[b][i];
        float kv = (float)((keepw[i >> 6] >> (i & 63)) & 1ull);
        out[OFF_KEEP + b * NN + si] = kv;
    }
}

/* ------------------------------------------------------------------ */
extern "C" void kernel_launch(void* const* d_in, const int* in_sizes, int n_in,
                              void* d_out, int out_size)
{
    (void)in_sizes; (void)n_in; (void)out_size;
    const float* logits  = (const float*)d_in[0];
    const float* deltas  = (const float*)d_in[1];
    const float* anchors = (const float*)d_in[2];
    float* out = (float*)d_out;

    cudaFuncSetAttribute(sort_kernel,
                         cudaFuncAttributeMaxDynamicSharedMemorySize,
                         NN * (int)sizeof(u64));
    int gsmem = (NW * 64 + 3 * NW) * (int)sizeof(u64) + 64 * (int)sizeof(int) + 256;
    cudaFuncSetAttribute(gather_kernel,
                         cudaFuncAttributeMaxDynamicSharedMemorySize, gsmem);

    prep_kernel<<<(BB * NN * 32 + 255) / 256, 256>>>(logits, deltas, anchors, out);
    sort_kernel<<<BB, 1024, NN * sizeof(u64)>>>();
    {
        dim3 grid(NW * (NW + 1) / 2, BB);
        mask_kernel<<<grid, 64>>>(out);
    }
    gather_kernel<<<BB, 1024, gsmem>>>(out);
}